// round 16
// baseline (speedup 1.0000x reference)
#include <cuda_runtime.h>
#include <cuda_fp16.h>
#include <math.h>
#include <stdint.h>

// Fixed shapes: B=4, N=4096 -> M=16384 rows, D=1024, Dff=4096
#define MROWS 16384
#define DDIM  1024
#define DFF   4096

// ---------------- scratch (device globals) ----------------------------------
__device__ __half g_xh [(size_t)MROWS * DDIM];
__device__ __half g_wvh[(size_t)DDIM  * DDIM];
__device__ __half g_w1h[(size_t)DDIM  * DFF];
__device__ __half g_w2h[(size_t)DFF   * DDIM];
__device__ __half g_hh [(size_t)MROWS * DDIM];
__device__ __half g_t2 [(size_t)MROWS * DFF];
__device__ float  g_t1 [(size_t)MROWS * DDIM];
__device__ float  g_hf [(size_t)MROWS * DDIM];
__device__ float  g_y3 [(size_t)MROWS * DDIM];

// ---------------- PTX helpers ------------------------------------------------
__device__ __forceinline__ uint32_t smem_u32(const void* p) {
    return (uint32_t)__cvta_generic_to_shared(p);
}
__device__ __forceinline__ void cp16(void* s, const void* g) {
    asm volatile("cp.async.cg.shared.global [%0], [%1], 16;\n"
                 :: "r"(smem_u32(s)), "l"(g));
}
__device__ __forceinline__ void cp_commit() {
    asm volatile("cp.async.commit_group;\n");
}
__device__ __forceinline__ void cp_wait0() {
    asm volatile("cp.async.wait_group 0;\n");
}
__device__ __forceinline__ void ldmA(uint32_t* r, const __half* p) {
    asm volatile("ldmatrix.sync.aligned.m8n8.x4.shared.b16 {%0,%1,%2,%3}, [%4];\n"
                 : "=r"(r[0]), "=r"(r[1]), "=r"(r[2]), "=r"(r[3])
                 : "r"(smem_u32(p)));
}
__device__ __forceinline__ void ldmBT(uint32_t* r, const __half* p) {
    asm volatile("ldmatrix.sync.aligned.m8n8.x4.trans.shared.b16 {%0,%1,%2,%3}, [%4];\n"
                 : "=r"(r[0]), "=r"(r[1]), "=r"(r[2]), "=r"(r[3])
                 : "r"(smem_u32(p)));
}
// f16-accumulate MMA: D = A*B + C, all f16 (2 output regs)
__device__ __forceinline__ void mma16816h(uint32_t* c, const uint32_t* a, const uint32_t* b) {
    asm volatile("mma.sync.aligned.m16n8k16.row.col.f16.f16.f16.f16 "
                 "{%0,%1}, {%2,%3,%4,%5}, {%6,%7}, {%0,%1};\n"
                 : "+r"(c[0]), "+r"(c[1])
                 : "r"(a[0]), "r"(a[1]), "r"(a[2]), "r"(a[3]),
                   "r"(b[0]), "r"(b[1]));
}
// f16 MMA with C = 0 (fresh chunk accumulator)
__device__ __forceinline__ void mma16816h0(uint32_t* d, const uint32_t* a, const uint32_t* b) {
    asm volatile("mma.sync.aligned.m16n8k16.row.col.f16.f16.f16.f16 "
                 "{%0,%1}, {%2,%3,%4,%5}, {%6,%7}, {%8,%8};\n"
                 : "=r"(d[0]), "=r"(d[1])
                 : "r"(a[0]), "r"(a[1]), "r"(a[2]), "r"(a[3]),
                   "r"(b[0]), "r"(b[1]), "r"(0u));
}
__device__ __forceinline__ float gelu_exact(float z) {
    return 0.5f * z * (1.0f + erff(z * 0.70710678118654752f));
}

// ---------------- fp32 -> fp16 flat convert ----------------------------------
__global__ void __launch_bounds__(256)
f2h_kernel(const float* __restrict__ in, __half* __restrict__ out, int n4) {
    int i = blockIdx.x * blockDim.x + threadIdx.x;
    if (i < n4) {
        float4 v = ((const float4*)in)[i];
        ((__half2*)out)[2 * i]     = __floats2half2_rn(v.x, v.y);
        ((__half2*)out)[2 * i + 1] = __floats2half2_rn(v.z, v.w);
    }
}

// ---------------- fp16 tensor-core GEMM, f16 accum (spill-free config) -------
// C[M,N] = A[M,K] @ B[K,N]. CTA 64x128, 4 warps (2x2) x 32x64 warp tile,
// BK=64, 2-stage cp.async, 3 CTAs/SM. f16 chunk accumulation (double-rate
// HMMA) with per-64K-chunk promotion to fp32 running sums.
// Register budget: fp32 acc 64 + f16 hacc 32 + frags/addr ~45 -> ~140 regs,
// under the 170 cap -- this is the FIRST spill-free f16-accum config
// (R12/R14 failed only because 64x64 tiles need 128+64 accumulator regs).
// Numerics measured in R12: rel_err 4.68e-4.
#define BM 64
#define BN 128
#define BK 64
#define STAGES 2
#define AP (BK + 8)   // 72 halves
#define BP (BN + 8)   // 136 halves
#define NTHR 128

template<int EPI>
__global__ void __launch_bounds__(NTHR, 3)
gemm16(const __half* __restrict__ A, const __half* __restrict__ Bm,
       int M, int N, int K,
       const float* __restrict__ bias, const float* __restrict__ resid,
       float* __restrict__ outF, __half* __restrict__ outH)
{
    extern __shared__ __half smem[];
    __half* sA = smem;                            // [STAGES][BM][AP]
    __half* sB = smem + (size_t)STAGES * BM * AP; // [STAGES][BK][BP]

    const int tid  = threadIdx.x;
    const int lane = tid & 31;
    const int warp = tid >> 5;   // 0..3
    const int wm   = warp >> 1;  // 0..1 -> m offset wm*32
    const int wn   = warp & 1;   // 0..1 -> n offset wn*64
    const int bm   = blockIdx.y * BM;
    const int bn   = blockIdx.x * BN;

    float acc[2][8][4];          // fp32 running sums (64 regs)
#pragma unroll
    for (int i = 0; i < 2; i++)
#pragma unroll
        for (int j = 0; j < 8; j++)
#pragma unroll
            for (int k = 0; k < 4; k++) acc[i][j][k] = 0.f;

    const int KT = K / BK;

    // A tile: 64 rows x 64 halves = 512 16B chunks -> 4/thread
    auto loadA = [&](int stage, int kt) {
        const __half* gA = A + (size_t)bm * K + (size_t)kt * BK;
        __half* s = sA + (size_t)stage * BM * AP;
#pragma unroll
        for (int i = 0; i < 4; i++) {
            int c = tid + i * NTHR;
            int r = c >> 3, col = (c & 7) * 8;
            cp16(s + r * AP + col, gA + (size_t)r * K + col);
        }
    };
    // B tile: 64 rows x 128 halves = 1024 16B chunks -> 8/thread
    auto loadB = [&](int stage, int kt) {
        const __half* gB = Bm + (size_t)kt * BK * N + bn;
        __half* s = sB + (size_t)stage * BK * BP;
#pragma unroll
        for (int i = 0; i < 8; i++) {
            int c = tid + i * NTHR;
            int r = c >> 4, col = (c & 15) * 8;
            cp16(s + r * BP + col, gB + (size_t)r * N + col);
        }
    };

    loadA(0, 0);
    loadB(0, 0);
    cp_commit();

    const int aRow = wm * 32 + (lane & 15);
    const int aCol = (lane >> 4) * 8;
    const int bRow = (lane & 15);
    const int bCol = wn * 64 + (lane >> 4) * 8;

    for (int kt = 0; kt < KT; ++kt) {
        cp_wait0();
        __syncthreads();

        if (kt + 1 < KT) {
            loadA((kt + 1) & 1, kt + 1);
            loadB((kt + 1) & 1, kt + 1);
            cp_commit();
        }

        const __half* csA = sA + (size_t)(kt & 1) * BM * AP;
        const __half* csB = sB + (size_t)(kt & 1) * BK * BP;

        uint32_t hacc[2][8][2];   // f16 chunk accumulators (32 regs)

#pragma unroll
        for (int ks = 0; ks < 4; ++ks) {           // four k16 steps per BK=64
            uint32_t af[2][4];
#pragma unroll
            for (int mt = 0; mt < 2; mt++)
                ldmA(af[mt], csA + (aRow + mt * 16) * AP + ks * 16 + aCol);
#pragma unroll
            for (int nq = 0; nq < 4; nq++) {
                uint32_t t[4];
                ldmBT(t, csB + (ks * 16 + bRow) * BP + bCol + nq * 16);
                if (ks == 0) {
#pragma unroll
                    for (int mt = 0; mt < 2; mt++) {
                        mma16816h0(hacc[mt][2 * nq],     af[mt], t);
                        mma16816h0(hacc[mt][2 * nq + 1], af[mt], t + 2);
                    }
                } else {
#pragma unroll
                    for (int mt = 0; mt < 2; mt++) {
                        mma16816h(hacc[mt][2 * nq],     af[mt], t);
                        mma16816h(hacc[mt][2 * nq + 1], af[mt], t + 2);
                    }
                }
            }
        }

        // promote f16 chunk partials into fp32 running sums
#pragma unroll
        for (int mt = 0; mt < 2; mt++)
#pragma unroll
            for (int nt = 0; nt < 8; nt++) {
                float2 lo = __half22float2(*(__half2*)&hacc[mt][nt][0]);
                float2 hi = __half22float2(*(__half2*)&hacc[mt][nt][1]);
                acc[mt][nt][0] += lo.x;
                acc[mt][nt][1] += lo.y;
                acc[mt][nt][2] += hi.x;
                acc[mt][nt][3] += hi.y;
            }
    }

    // epilogue
    const int r0 = bm + wm * 32 + (lane >> 2);
    const int c0 = bn + wn * 64 + 2 * (lane & 3);
#pragma unroll
    for (int mt = 0; mt < 2; mt++) {
#pragma unroll
        for (int nt = 0; nt < 8; nt++) {
            const float* a4 = acc[mt][nt];
            int c = c0 + nt * 8;
            float b0 = bias[c], b1 = bias[c + 1];
#pragma unroll
            for (int half_ = 0; half_ < 2; half_++) {
                int r = r0 + mt * 16 + half_ * 8;
                size_t idx = (size_t)r * N + c;
                float v0 = a4[2 * half_ + 0] + b0;
                float v1 = a4[2 * half_ + 1] + b1;
                if (EPI == 0) {
                    float2 rr = *(const float2*)(resid + idx);
                    float2 o; o.x = v0 + rr.x; o.y = v1 + rr.y;
                    *(float2*)(outF + idx) = o;
                } else {
                    *(__half2*)(outH + idx) =
                        __floats2half2_rn(gelu_exact(v0), gelu_exact(v1));
                }
            }
        }
    }
}

// ---------------- row LayerNorm (D=1024) -------------------------------------
__global__ void __launch_bounds__(256)
ln1024(const float* __restrict__ in, const float* __restrict__ g,
       const float* __restrict__ b, float* __restrict__ outF,
       __half* __restrict__ outH)
{
    __shared__ float sh[16];
    const int row = blockIdx.x, tid = threadIdx.x;
    const int lane = tid & 31, warp = tid >> 5;

    const float4 v = ((const float4*)(in + (size_t)row * DDIM))[tid];
    float s = v.x + v.y + v.z + v.w;
#pragma unroll
    for (int o = 16; o; o >>= 1) s += __shfl_xor_sync(0xffffffffu, s, o);
    if (lane == 0) sh[warp] = s;
    __syncthreads();
    float mean = 0.f;
#pragma unroll
    for (int i = 0; i < 8; i++) mean += sh[i];
    mean *= (1.0f / DDIM);

    float d0 = v.x - mean, d1 = v.y - mean, d2 = v.z - mean, d3 = v.w - mean;
    float q = d0*d0 + d1*d1 + d2*d2 + d3*d3;
#pragma unroll
    for (int o = 16; o; o >>= 1) q += __shfl_xor_sync(0xffffffffu, q, o);
    if (lane == 0) sh[8 + warp] = q;
    __syncthreads();
    float var = 0.f;
#pragma unroll
    for (int i = 0; i < 8; i++) var += sh[8 + i];
    var *= (1.0f / DDIM);
    const float rstd = rsqrtf(var + 1e-5f);

    const float4 gg = ((const float4*)g)[tid];
    const float4 bb = ((const float4*)b)[tid];
    float y0 = d0 * rstd * gg.x + bb.x;
    float y1 = d1 * rstd * gg.y + bb.y;
    float y2 = d2 * rstd * gg.z + bb.z;
    float y3 = d3 * rstd * gg.w + bb.w;

    if (outF) ((float4*)(outF + (size_t)row * DDIM))[tid] = make_float4(y0, y1, y2, y3);
    if (outH) {
        __half2* o = (__half2*)(outH + (size_t)row * DDIM);
        o[2 * tid]     = __floats2half2_rn(y0, y1);
        o[2 * tid + 1] = __floats2half2_rn(y2, y3);
    }
}

// ---------------- launch ------------------------------------------------------
extern "C" void kernel_launch(void* const* d_in, const int* in_sizes, int n_in,
                              void* d_out, int out_size)
{
    const float* x   = (const float*)d_in[0];
    const float* Wv  = (const float*)d_in[6];
    const float* bv  = (const float*)d_in[7];
    const float* g1  = (const float*)d_in[8];
    const float* be1 = (const float*)d_in[9];
    const float* W1  = (const float*)d_in[10];
    const float* bf1 = (const float*)d_in[11];
    const float* W2  = (const float*)d_in[12];
    const float* bf2 = (const float*)d_in[13];
    const float* g2  = (const float*)d_in[14];
    const float* be2 = (const float*)d_in[15];
    float* out = (float*)d_out;

    __half *xh, *wvh, *w1h, *w2h, *hh, *t2;
    float *t1, *hf, *y3;
    cudaGetSymbolAddress((void**)&xh,  g_xh);
    cudaGetSymbolAddress((void**)&wvh, g_wvh);
    cudaGetSymbolAddress((void**)&w1h, g_w1h);
    cudaGetSymbolAddress((void**)&w2h, g_w2h);
    cudaGetSymbolAddress((void**)&hh,  g_hh);
    cudaGetSymbolAddress((void**)&t2,  g_t2);
    cudaGetSymbolAddress((void**)&t1,  g_t1);
    cudaGetSymbolAddress((void**)&hf,  g_hf);
    cudaGetSymbolAddress((void**)&y3,  g_y3);

    const int SMEM = STAGES * (BM * AP + BK * BP) * (int)sizeof(__half); // 53248
    cudaFuncSetAttribute(gemm16<0>, cudaFuncAttributeMaxDynamicSharedMemorySize, SMEM);
    cudaFuncSetAttribute(gemm16<1>, cudaFuncAttributeMaxDynamicSharedMemorySize, SMEM);

    dim3 blk(NTHR);
    // gemm1 kept at launch index 3 (ncu capture window).
    f2h_kernel<<<(MROWS * DDIM / 4 + 255) / 256, 256>>>(x,  xh,  MROWS * DDIM / 4);  // 0
    f2h_kernel<<<(DDIM  * DDIM / 4 + 255) / 256, 256>>>(Wv, wvh, DDIM * DDIM / 4);   // 1
    f2h_kernel<<<(DDIM  * DFF  / 4 + 255) / 256, 256>>>(W1, w1h, DDIM * DFF / 4);    // 2
    // GEMM1 (index 3): t1 = x + x@Wv + bv
    gemm16<0><<<dim3(DDIM / BN, MROWS / BM), blk, SMEM>>>(
        xh, wvh, MROWS, DDIM, DDIM, bv, x, t1, nullptr);
    f2h_kernel<<<(DFF   * DDIM / 4 + 255) / 256, 256>>>(W2, w2h, DFF * DDIM / 4);    // 4
    // LN1 -> h (fp32 + fp16)
    ln1024<<<MROWS, 256>>>(t1, g1, be1, hf, hh);
    // GEMM2: t2 = gelu(h@W1 + bf1)
    gemm16<1><<<dim3(DFF / BN, MROWS / BM), blk, SMEM>>>(
        hh, w1h, MROWS, DFF, DDIM, bf1, nullptr, nullptr, t2);
    // GEMM3: y3 = h + t2@W2 + bf2
    gemm16<0><<<dim3(DDIM / BN, MROWS / BM), blk, SMEM>>>(
        t2, w2h, MROWS, DDIM, DFF, bf2, hf, y3, nullptr);
    // LN2 -> out
    ln1024<<<MROWS, 256>>>(y3, g2, be2, out, nullptr);
}

// round 17
// speedup vs baseline: 1.2102x; 1.2102x over previous
#include <cuda_runtime.h>
#include <cuda_fp16.h>
#include <math.h>
#include <stdint.h>

// Fixed shapes: B=4, N=4096 -> M=16384 rows, D=1024, Dff=4096
#define MROWS 16384
#define DDIM  1024
#define DFF   4096

// ---------------- scratch (device globals) ----------------------------------
__device__ __half g_xh [(size_t)MROWS * DDIM];
__device__ __half g_wvh[(size_t)DDIM  * DDIM];
__device__ __half g_w1h[(size_t)DDIM  * DFF];
__device__ __half g_w2h[(size_t)DFF   * DDIM];
__device__ __half g_hh [(size_t)MROWS * DDIM];
__device__ __half g_t2 [(size_t)MROWS * DFF];
__device__ float  g_t1 [(size_t)MROWS * DDIM];
__device__ float  g_y3 [(size_t)MROWS * DDIM];

// ---------------- PTX helpers ------------------------------------------------
__device__ __forceinline__ uint32_t smem_u32(const void* p) {
    return (uint32_t)__cvta_generic_to_shared(p);
}
__device__ __forceinline__ void cp16(void* s, const void* g) {
    asm volatile("cp.async.cg.shared.global [%0], [%1], 16;\n"
                 :: "r"(smem_u32(s)), "l"(g));
}
__device__ __forceinline__ void cp_commit() {
    asm volatile("cp.async.commit_group;\n");
}
__device__ __forceinline__ void cp_wait0() {
    asm volatile("cp.async.wait_group 0;\n");
}
__device__ __forceinline__ void ldmA(uint32_t* r, const __half* p) {
    asm volatile("ldmatrix.sync.aligned.m8n8.x4.shared.b16 {%0,%1,%2,%3}, [%4];\n"
                 : "=r"(r[0]), "=r"(r[1]), "=r"(r[2]), "=r"(r[3])
                 : "r"(smem_u32(p)));
}
__device__ __forceinline__ void ldmBT(uint32_t* r, const __half* p) {
    asm volatile("ldmatrix.sync.aligned.m8n8.x4.trans.shared.b16 {%0,%1,%2,%3}, [%4];\n"
                 : "=r"(r[0]), "=r"(r[1]), "=r"(r[2]), "=r"(r[3])
                 : "r"(smem_u32(p)));
}
__device__ __forceinline__ void mma16816(float* c, const uint32_t* a, const uint32_t* b) {
    asm volatile("mma.sync.aligned.m16n8k16.row.col.f32.f16.f16.f32 "
                 "{%0,%1,%2,%3}, {%4,%5,%6,%7}, {%8,%9}, {%0,%1,%2,%3};\n"
                 : "+f"(c[0]), "+f"(c[1]), "+f"(c[2]), "+f"(c[3])
                 : "r"(a[0]), "r"(a[1]), "r"(a[2]), "r"(a[3]),
                   "r"(b[0]), "r"(b[1]));
}
__device__ __forceinline__ float gelu_exact(float z) {
    return 0.5f * z * (1.0f + erff(z * 0.70710678118654752f));
}

// ---------------- fp32 -> fp16 flat convert ----------------------------------
__global__ void __launch_bounds__(256)
f2h_kernel(const float* __restrict__ in, __half* __restrict__ out, int n4) {
    int i = blockIdx.x * blockDim.x + threadIdx.x;
    if (i < n4) {
        float4 v = ((const float4*)in)[i];
        ((__half2*)out)[2 * i]     = __floats2half2_rn(v.x, v.y);
        ((__half2*)out)[2 * i + 1] = __floats2half2_rn(v.z, v.w);
    }
}

// ---------------- fp16 tensor-core GEMM (mma.sync, fp32 accum) ---------------
// C[M,N] = A[M,K] @ B[K,N]. BN=128, BK=64, 2-stage cp.async, 4 warps (2x2).
//   BMT=128: warp tile 64x64, 3 CTAs/SM (regs ~168) -- best for gemm2/gemm3
//   BMT=64 : warp tile 32x64, 4 CTAs/SM (regs ~128) -- best tail for gemm1
// EPI==0: outF = acc + bias[n] + residF (fp32 resid)
// EPI==1: outH = (half) gelu(acc + bias)
// EPI==2: outF = acc + bias[n] + residH (fp16 resid)
#define BN 128
#define BK 64
#define AP (BK + 8)   // 72 halves
#define BP (BN + 8)   // 136 halves
#define NTHR 128

template<int EPI, int BMT>
__global__ void __launch_bounds__(NTHR, (BMT == 128) ? 3 : 4)
gemm16(const __half* __restrict__ A, const __half* __restrict__ Bm,
       int M, int N, int K,
       const float* __restrict__ bias,
       const float* __restrict__ residF, const __half* __restrict__ residH,
       float* __restrict__ outF, __half* __restrict__ outH)
{
    constexpr int MT  = BMT / 32;       // m-subtiles per warp (4 or 2)
    constexpr int WMO = BMT / 2;        // warp m-offset unit
    constexpr int ACH = BMT / 16;       // A 16B-chunks per thread (8 or 4)

    extern __shared__ __half smem[];
    __half* sA = smem;                          // [2][BMT][AP]
    __half* sB = smem + (size_t)2 * BMT * AP;   // [2][BK][BP]

    const int tid  = threadIdx.x;
    const int lane = tid & 31;
    const int warp = tid >> 5;   // 0..3
    const int wm   = warp >> 1;  // 0..1
    const int wn   = warp & 1;   // 0..1
    const int bm   = blockIdx.y * BMT;
    const int bn   = blockIdx.x * BN;

    float acc[MT][8][4];
#pragma unroll
    for (int i = 0; i < MT; i++)
#pragma unroll
        for (int j = 0; j < 8; j++)
#pragma unroll
            for (int k = 0; k < 4; k++) acc[i][j][k] = 0.f;

    const int KT = K / BK;

    auto loadA = [&](int stage, int kt) {
        const __half* gA = A + (size_t)bm * K + (size_t)kt * BK;
        __half* s = sA + (size_t)stage * BMT * AP;
#pragma unroll
        for (int i = 0; i < ACH; i++) {
            int c = tid + i * NTHR;
            int r = c >> 3, col = (c & 7) * 8;
            cp16(s + r * AP + col, gA + (size_t)r * K + col);
        }
    };
    auto loadB = [&](int stage, int kt) {
        const __half* gB = Bm + (size_t)kt * BK * N + bn;
        __half* s = sB + (size_t)stage * BK * BP;
#pragma unroll
        for (int i = 0; i < 8; i++) {
            int c = tid + i * NTHR;
            int r = c >> 4, col = (c & 15) * 8;
            cp16(s + r * BP + col, gB + (size_t)r * N + col);
        }
    };

    loadA(0, 0);
    loadB(0, 0);
    cp_commit();

    const int aRow = wm * WMO + (lane & 15);
    const int aCol = (lane >> 4) * 8;
    const int bRow = (lane & 15);
    const int bCol = wn * 64 + (lane >> 4) * 8;

    for (int kt = 0; kt < KT; ++kt) {
        cp_wait0();
        __syncthreads();

        if (kt + 1 < KT) {
            loadA((kt + 1) & 1, kt + 1);
            loadB((kt + 1) & 1, kt + 1);
            cp_commit();
        }

        const __half* csA = sA + (size_t)(kt & 1) * BMT * AP;
        const __half* csB = sB + (size_t)(kt & 1) * BK * BP;

#pragma unroll
        for (int ks = 0; ks < 4; ++ks) {           // four k16 steps per BK=64
            uint32_t af[MT][4];
#pragma unroll
            for (int mt = 0; mt < MT; mt++)
                ldmA(af[mt], csA + (aRow + mt * 16) * AP + ks * 16 + aCol);
#pragma unroll
            for (int nq = 0; nq < 4; nq++) {       // JIT B fragment
                uint32_t t[4];
                ldmBT(t, csB + (ks * 16 + bRow) * BP + bCol + nq * 16);
#pragma unroll
                for (int mt = 0; mt < MT; mt++) {
                    mma16816(acc[mt][2 * nq],     af[mt], t);
                    mma16816(acc[mt][2 * nq + 1], af[mt], t + 2);
                }
            }
        }
    }

    // epilogue
    const int r0 = bm + wm * WMO + (lane >> 2);
    const int c0 = bn + wn * 64 + 2 * (lane & 3);
#pragma unroll
    for (int mt = 0; mt < MT; mt++) {
#pragma unroll
        for (int nt = 0; nt < 8; nt++) {
            const float* a4 = acc[mt][nt];
            int c = c0 + nt * 8;
            float b0 = bias[c], b1 = bias[c + 1];
#pragma unroll
            for (int half_ = 0; half_ < 2; half_++) {
                int r = r0 + mt * 16 + half_ * 8;
                size_t idx = (size_t)r * N + c;
                float v0 = a4[2 * half_ + 0] + b0;
                float v1 = a4[2 * half_ + 1] + b1;
                if (EPI == 0) {
                    float2 rr = *(const float2*)(residF + idx);
                    float2 o; o.x = v0 + rr.x; o.y = v1 + rr.y;
                    *(float2*)(outF + idx) = o;
                } else if (EPI == 2) {
                    float2 rr = __half22float2(*(const __half2*)(residH + idx));
                    float2 o; o.x = v0 + rr.x; o.y = v1 + rr.y;
                    *(float2*)(outF + idx) = o;
                } else {
                    *(__half2*)(outH + idx) =
                        __floats2half2_rn(gelu_exact(v0), gelu_exact(v1));
                }
            }
        }
    }
}

// ---------------- row LayerNorm (D=1024) -------------------------------------
__global__ void __launch_bounds__(256)
ln1024(const float* __restrict__ in, const float* __restrict__ g,
       const float* __restrict__ b, float* __restrict__ outF,
       __half* __restrict__ outH)
{
    __shared__ float sh[16];
    const int row = blockIdx.x, tid = threadIdx.x;
    const int lane = tid & 31, warp = tid >> 5;

    const float4 v = ((const float4*)(in + (size_t)row * DDIM))[tid];
    float s = v.x + v.y + v.z + v.w;
#pragma unroll
    for (int o = 16; o; o >>= 1) s += __shfl_xor_sync(0xffffffffu, s, o);
    if (lane == 0) sh[warp] = s;
    __syncthreads();
    float mean = 0.f;
#pragma unroll
    for (int i = 0; i < 8; i++) mean += sh[i];
    mean *= (1.0f / DDIM);

    float d0 = v.x - mean, d1 = v.y - mean, d2 = v.z - mean, d3 = v.w - mean;
    float q = d0*d0 + d1*d1 + d2*d2 + d3*d3;
#pragma unroll
    for (int o = 16; o; o >>= 1) q += __shfl_xor_sync(0xffffffffu, q, o);
    if (lane == 0) sh[8 + warp] = q;
    __syncthreads();
    float var = 0.f;
#pragma unroll
    for (int i = 0; i < 8; i++) var += sh[8 + i];
    var *= (1.0f / DDIM);
    const float rstd = rsqrtf(var + 1e-5f);

    const float4 gg = ((const float4*)g)[tid];
    const float4 bb = ((const float4*)b)[tid];
    float y0 = d0 * rstd * gg.x + bb.x;
    float y1 = d1 * rstd * gg.y + bb.y;
    float y2 = d2 * rstd * gg.z + bb.z;
    float y3 = d3 * rstd * gg.w + bb.w;

    if (outF) ((float4*)(outF + (size_t)row * DDIM))[tid] = make_float4(y0, y1, y2, y3);
    if (outH) {
        __half2* o = (__half2*)(outH + (size_t)row * DDIM);
        o[2 * tid]     = __floats2half2_rn(y0, y1);
        o[2 * tid + 1] = __floats2half2_rn(y2, y3);
    }
}

// ---------------- launch ------------------------------------------------------
extern "C" void kernel_launch(void* const* d_in, const int* in_sizes, int n_in,
                              void* d_out, int out_size)
{
    const float* x   = (const float*)d_in[0];
    const float* Wv  = (const float*)d_in[6];
    const float* bv  = (const float*)d_in[7];
    const float* g1  = (const float*)d_in[8];
    const float* be1 = (const float*)d_in[9];
    const float* W1  = (const float*)d_in[10];
    const float* bf1 = (const float*)d_in[11];
    const float* W2  = (const float*)d_in[12];
    const float* bf2 = (const float*)d_in[13];
    const float* g2  = (const float*)d_in[14];
    const float* be2 = (const float*)d_in[15];
    float* out = (float*)d_out;

    __half *xh, *wvh, *w1h, *w2h, *hh, *t2;
    float *t1, *y3;
    cudaGetSymbolAddress((void**)&xh,  g_xh);
    cudaGetSymbolAddress((void**)&wvh, g_wvh);
    cudaGetSymbolAddress((void**)&w1h, g_w1h);
    cudaGetSymbolAddress((void**)&w2h, g_w2h);
    cudaGetSymbolAddress((void**)&hh,  g_hh);
    cudaGetSymbolAddress((void**)&t2,  g_t2);
    cudaGetSymbolAddress((void**)&t1,  g_t1);
    cudaGetSymbolAddress((void**)&y3,  g_y3);

    // BMT=64:  smem = 2*(64*72  + 64*136)*2 = 53248   (4 CTAs/SM)
    // BMT=128: smem = 2*(128*72 + 64*136)*2 = 71680   (3 CTAs/SM)
    const int SM64  = 2 * (64  * AP + BK * BP) * (int)sizeof(__half);
    const int SM128 = 2 * (128 * AP + BK * BP) * (int)sizeof(__half);
    cudaFuncSetAttribute((gemm16<0,  64>), cudaFuncAttributeMaxDynamicSharedMemorySize, SM64);
    cudaFuncSetAttribute((gemm16<1, 128>), cudaFuncAttributeMaxDynamicSharedMemorySize, SM128);
    cudaFuncSetAttribute((gemm16<2, 128>), cudaFuncAttributeMaxDynamicSharedMemorySize, SM128);

    dim3 blk(NTHR);
    // gemm1 kept at launch index 3 (ncu capture window).
    f2h_kernel<<<(MROWS * DDIM / 4 + 255) / 256, 256>>>(x,  xh,  MROWS * DDIM / 4);  // 0
    f2h_kernel<<<(DDIM  * DDIM / 4 + 255) / 256, 256>>>(Wv, wvh, DDIM * DDIM / 4);   // 1
    f2h_kernel<<<(DDIM  * DFF  / 4 + 255) / 256, 256>>>(W1, w1h, DDIM * DFF / 4);    // 2
    // GEMM1 (index 3): t1 = x + x@Wv + bv  [BMT=64: 2048 CTAs, measured 110.4us]
    gemm16<0, 64><<<dim3(DDIM / BN, MROWS / 64), blk, SM64>>>(
        xh, wvh, MROWS, DDIM, DDIM, bv, x, nullptr, t1, nullptr);
    f2h_kernel<<<(DFF   * DDIM / 4 + 255) / 256, 256>>>(W2, w2h, DFF * DDIM / 4);    // 4
    // LN1 -> h (fp16 only; saves the 64MB fp32 hf write)
    ln1024<<<MROWS, 256>>>(t1, g1, be1, nullptr, hh);
    // GEMM2: t2 = gelu(h@W1 + bf1)  [BMT=128: best measured shape]
    gemm16<1, 128><<<dim3(DFF / BN, MROWS / 128), blk, SM128>>>(
        hh, w1h, MROWS, DFF, DDIM, bf1, nullptr, nullptr, nullptr, t2);
    // GEMM3: y3 = h + t2@W2 + bf2   [BMT=128; fp16 residual (R13-proven path)]
    gemm16<2, 128><<<dim3(DDIM / BN, MROWS / 128), blk, SM128>>>(
        t2, w2h, MROWS, DDIM, DFF, bf2, nullptr, hh, y3, nullptr);
    // LN2 -> out
    ln1024<<<MROWS, 256>>>(y3, g2, be2, out, nullptr);
}